// round 15
// baseline (speedup 1.0000x reference)
#include <cuda_runtime.h>
#include <cuda_fp16.h>
#include <cstdint>

// ---------------------------------------------------------------------------
// PCGen on GB300 (sm_103 baseline ISA): fp16 2-way-split mma.sync GEMMs.
// Tile 128o x 128m, chunk-32 (PITCH 80) double-buffered cp.async pipeline,
// ONE barrier per chunk, 2 CTAs/SM. Packed f16x2 converts in staging paths.
// BN stats fused into GEMM epilogue; packed-float4 kNN filter (unroll 4).
// B=32, M=2048, CW=512.
// ---------------------------------------------------------------------------

#define BATCH 32
#define MPTS  2048
#define CW    512

// ---------------- scratch (static device memory; no allocs allowed) --------
__device__ float  g_t0 [BATCH * 512 * MPTS];
__device__ float  g_t1 [BATCH * 256 * MPTS];
__device__ float  g_t2 [BATCH * 128 * MPTS];
__device__ float  g_t3 [BATCH * 64  * MPTS];
__device__ float4 g_pk [BATCH * MPTS];           // packed (x,y,z,|p|^2)
__device__ float  g_aff_a[4 * 512];
__device__ float  g_aff_c[4 * 512];
__device__ float  g_part[2 * 512 * 2048];        // BN partials [2*oc][part]
__device__ __half g_xnH[BATCH * MPTS * 16],  g_xnL[BATCH * MPTS * 16];
__device__ __half g_y1H[BATCH * MPTS * 256], g_y1L[BATCH * MPTS * 256];
__device__ __half g_y2H[BATCH * MPTS * 512], g_y2L[BATCH * MPTS * 512];
#define NW_TOT 569344
__device__ __half g_WH[NW_TOT], g_WL[NW_TOT];
// weight offsets: L1, L2, c0, c1, c2, c3
#define WO_1 0
#define WO_2 4096
#define WO_3 135168
#define WO_4 397312
#define WO_5 528384
#define WO_6 561152

__device__ __forceinline__ uint32_t smem_u32(const void* p) {
    uint32_t a;
    asm("{ .reg .u64 t; cvta.to.shared.u64 t, %1; cvt.u32.u64 %0, t; }"
        : "=r"(a) : "l"(p));
    return a;
}

// pack 2 fp32 -> half2 (round-nearest, same as __float2half_rn elementwise)
__device__ __forceinline__ uint32_t f2h2(float lo, float hi) {
    uint32_t r;
    asm("cvt.rn.f16x2.f32 %0, %1, %2;" : "=r"(r) : "f"(hi), "f"(lo));
    return r;
}
__device__ __forceinline__ float2 h2f2(uint32_t h) {
    __half2 hv = *(__half2*)&h;
    return __half22float2(hv);
}

#define LDSM4(r0, r1, r2, r3, addr) \
    asm volatile("ldmatrix.sync.aligned.m8n8.x4.shared.b16 {%0,%1,%2,%3}, [%4];" \
                 : "=r"(r0), "=r"(r1), "=r"(r2), "=r"(r3) : "r"(addr))
#define LDSM2(r0, r1, addr) \
    asm volatile("ldmatrix.sync.aligned.m8n8.x2.shared.b16 {%0,%1}, [%2];" \
                 : "=r"(r0), "=r"(r1) : "r"(addr))
#define MMA_FP16(d, a0, a1, a2, a3, b0, b1) \
    asm volatile("mma.sync.aligned.m16n8k16.row.col.f32.f16.f16.f32 " \
                 "{%0,%1,%2,%3}, {%4,%5,%6,%7}, {%8,%9}, {%0,%1,%2,%3};" \
                 : "+f"((d)[0]), "+f"((d)[1]), "+f"((d)[2]), "+f"((d)[3]) \
                 : "r"(a0), "r"(a1), "r"(a2), "r"(a3), "r"(b0), "r"(b1))
#define CP16(saddr, gptr) \
    asm volatile("cp.async.cg.shared.global [%0], [%1], 16;" \
                 :: "r"(saddr), "l"(__cvta_generic_to_global(gptr)))
#define CP_COMMIT() asm volatile("cp.async.commit_group;" ::: "memory")
#define CP_WAIT0()  asm volatile("cp.async.wait_group 0;" ::: "memory")

// split 4 fp32 -> (hi half2x2, lo half2x2) using packed converts
__device__ __forceinline__ void split4(const float* v, uint2& hi, uint2& lo) {
    hi.x = f2h2(v[0], v[1]);
    hi.y = f2h2(v[2], v[3]);
    float2 h01 = h2f2(hi.x), h23 = h2f2(hi.y);
    lo.x = f2h2(v[0] - h01.x, v[1] - h01.y);
    lo.y = f2h2(v[2] - h23.x, v[3] - h23.y);
}

// ---------------- fused prep: 6 weight splits + sample normalize ------------
__device__ __forceinline__ void wsplit_seg(const float* w, __half* WH,
                                           __half* WL, int n, int blk)
{
    int i = blk * 256 + threadIdx.x;
    if (i >= n) return;
    float v = w[i];
    __half h = __float2half_rn(v);
    WH[i] = h;
    WL[i] = __float2half_rn(v - __half2float(h));
}

__global__ void prep_kernel(const float* __restrict__ w1, const float* __restrict__ w2,
                            const float* __restrict__ w3, const float* __restrict__ w4,
                            const float* __restrict__ w5, const float* __restrict__ w6,
                            __half* __restrict__ WH, __half* __restrict__ WL,
                            const float* __restrict__ s,
                            __half* __restrict__ XH, __half* __restrict__ XL)
{
    int bk = blockIdx.x;
    if (bk < 16)        { wsplit_seg(w1, WH + WO_1, WL + WO_1, 4096,   bk);        return; }
    if (bk < 528)       { wsplit_seg(w2, WH + WO_2, WL + WO_2, 131072, bk - 16);   return; }
    if (bk < 1552)      { wsplit_seg(w3, WH + WO_3, WL + WO_3, 262144, bk - 528);  return; }
    if (bk < 2064)      { wsplit_seg(w4, WH + WO_4, WL + WO_4, 131072, bk - 1552); return; }
    if (bk < 2192)      { wsplit_seg(w5, WH + WO_5, WL + WO_5, 32768,  bk - 2064); return; }
    if (bk < 2224)      { wsplit_seg(w6, WH + WO_6, WL + WO_6, 8192,   bk - 2192); return; }

    // norm_split segment: blocks [2224, 2480)
    int idx = (bk - 2224) * 256 + threadIdx.x;
    int b = idx >> 11, m = idx & (MPTS - 1);
    const float* p = s + (size_t)b * 16 * MPTS + m;
    float v[16]; float ss = 0.f;
#pragma unroll
    for (int c = 0; c < 16; ++c) { v[c] = p[c * MPTS]; ss = fmaf(v[c], v[c], ss); }
    float inv = rsqrtf(ss);
#pragma unroll
    for (int c = 0; c < 16; ++c) v[c] *= inv;
    size_t base = (size_t)idx * 16;
#pragma unroll
    for (int q = 0; q < 4; ++q) {
        uint2 hi, lo;
        split4(v + q * 4, hi, lo);
        *(uint2*)(XH + base + q * 4) = hi;
        *(uint2*)(XL + base + q * 4) = lo;
    }
}

// ============ fp16-split tensor GEMM, chunk-32 double-buffered =============
// Y[b][o][m] = sum_k W[o][k] * f(X[b][k][m]) (+bias, epilogue)
// Tile OT x 128m. 256 thr = 8 warps (2o x 4m); warp tile (OT/2) x 32.
template <int OT, int XMODE, int EPI>
__global__ __launch_bounds__(256, 2)
void gemm_mma(const __half* __restrict__ XH, const __half* __restrict__ XL,
              const float* __restrict__ Xf,
              const __half* __restrict__ WHg, const __half* __restrict__ WLg,
              const float* __restrict__ bias,
              float* __restrict__ Yf,
              __half* __restrict__ YH, __half* __restrict__ YL,
              int Cin, int Cout,
              const float* __restrict__ pa, const float* __restrict__ pc,
              const float* __restrict__ zmod,
              float* __restrict__ part)
{
    extern __shared__ char smem[];
    constexpr int PITCH = 80;                   // 32 fp16 + 16B pad
    constexpr int OW  = OT / 2;
    constexpr int OFR = OT / 32;
    constexpr uint32_t OFF_WLO = (uint32_t)OT * PITCH;
    constexpr uint32_t OFF_XHI = 2u * OT * PITCH;
    constexpr uint32_t OFF_XLO = OFF_XHI + 128u * PITCH;
    constexpr uint32_t STAGE   = OFF_XHI + 2u * 128u * PITCH;

    const int tid  = threadIdx.x;
    const int lane = tid & 31;
    const int wid  = tid >> 5;
    const int warp_m = wid & 3;
    const int warp_o = wid >> 2;

    const int b  = blockIdx.z;
    const int m0 = blockIdx.x * 128;
    const int o0 = blockIdx.y * OT;
    const uint32_t sbase = smem_u32(smem);

    float acc[OFR][4][4];
#pragma unroll
    for (int i = 0; i < OFR; ++i)
#pragma unroll
        for (int j = 0; j < 4; ++j)
#pragma unroll
            for (int k = 0; k < 4; ++k) acc[i][j][k] = 0.f;

    const uint32_t aOff = (uint32_t)((warp_o * OW + (lane & 15)) * PITCH
                                     + ((lane >> 4) << 4));
    const uint32_t bOff = OFF_XHI + (uint32_t)((warp_m * 32 + (lane & 7)) * PITCH
                                     + (((lane >> 3) & 1) << 4));

    const int nch = (Cin + 31) >> 5;

    auto issue_chunk = [&](int c) {
        const int k0 = c * 32;
        const int kcnt = (Cin - k0 < 32) ? (Cin - k0) : 32;   // 16 or 32
        const int cprsh = (kcnt == 32) ? 2 : 1;
        const int cpr = 1 << cprsh;
        const uint32_t so = sbase + (uint32_t)(c & 1) * STAGE;
        for (int i = tid; i < (OT << cprsh); i += 256) {
            int o = i >> cprsh, p = i & (cpr - 1);
            uint32_t soff = so + (uint32_t)(o * PITCH + p * 16);
            size_t goff = (size_t)(o0 + o) * Cin + k0 + p * 8;
            CP16(soff, WHg + goff);
            CP16(soff + OFF_WLO, WLg + goff);
        }
        if (XMODE == 0) {
            for (int i = tid; i < (128 << cprsh); i += 256) {
                int m = i >> cprsh, p = i & (cpr - 1);
                uint32_t soff = so + OFF_XHI + (uint32_t)(m * PITCH + p * 16);
                size_t goff = ((size_t)b * MPTS + m0 + m) * Cin + k0 + p * 8;
                CP16(soff, XH + goff);
                CP16(soff + 128u * PITCH, XL + goff);
            }
        }
        CP_COMMIT();
    };

    auto convert_chunk = [&](int c) {
        const int k0 = c * 32;
        const int kcnt = (Cin - k0 < 32) ? (Cin - k0) : 32;
        const int nq = kcnt >> 2;
        const uint32_t so = (uint32_t)(c & 1) * STAGE;
        char* Xhi = smem + so + OFF_XHI;
        char* Xlo = smem + so + OFF_XLO;
        const float* Xb = Xf + (size_t)b * Cin * MPTS;
        for (int i = tid; i < (nq << 7); i += 256) {
            int m = i & 127, kq = i >> 7;
            int kg = k0 + 4 * kq;
            const float* xp = Xb + (size_t)kg * MPTS + m0 + m;
            float v[4];
#pragma unroll
            for (int j = 0; j < 4; ++j) {
                float t = xp[(size_t)j * MPTS];
                v[j] = fmaxf(fmaf(pa[kg + j], t, pc[kg + j]), 0.f);
            }
            uint2 hi, lo;
            split4(v, hi, lo);
            uint32_t off = (uint32_t)(m * PITCH + kq * 8);
            *(uint2*)(Xhi + off) = hi;
            *(uint2*)(Xlo + off) = lo;
        }
    };

    // ---- pipeline ----
    issue_chunk(0);
    if (XMODE == 1) convert_chunk(0);

    for (int c = 0; c < nch; ++c) {
        CP_WAIT0();
        __syncthreads();
        if (c + 1 < nch) {
            issue_chunk(c + 1);
            if (XMODE == 1) convert_chunk(c + 1);
        }

        const int k0 = c * 32;
        const int kcnt = (Cin - k0 < 32) ? (Cin - k0) : 32;
        const uint32_t so = sbase + (uint32_t)(c & 1) * STAGE;
        const uint32_t aHi = so + aOff;
        const uint32_t aLo = aHi + OFF_WLO;
        const uint32_t bHi = so + bOff;
        const uint32_t bLo = bHi + 128u * PITCH;

        const int ksteps = kcnt >> 4;
        for (int ks = 0; ks < ksteps; ++ks) {
            const uint32_t ko = (uint32_t)ks * 32;
            uint32_t bh[4][2], bl[4][2];
#pragma unroll
            for (int mf = 0; mf < 4; ++mf) {
                LDSM2(bh[mf][0], bh[mf][1], bHi + mf * (8 * PITCH) + ko);
                LDSM2(bl[mf][0], bl[mf][1], bLo + mf * (8 * PITCH) + ko);
            }
#pragma unroll
            for (int of = 0; of < OFR; ++of) {
                uint32_t ah[4], al[4];
                LDSM4(ah[0], ah[1], ah[2], ah[3], aHi + of * (16 * PITCH) + ko);
                LDSM4(al[0], al[1], al[2], al[3], aLo + of * (16 * PITCH) + ko);
#pragma unroll
                for (int mf = 0; mf < 4; ++mf)
                    MMA_FP16(acc[of][mf], ah[0], ah[1], ah[2], ah[3],
                             bh[mf][0], bh[mf][1]);
#pragma unroll
                for (int mf = 0; mf < 4; ++mf)
                    MMA_FP16(acc[of][mf], al[0], al[1], al[2], al[3],
                             bh[mf][0], bh[mf][1]);
#pragma unroll
                for (int mf = 0; mf < 4; ++mf)
                    MMA_FP16(acc[of][mf], ah[0], ah[1], ah[2], ah[3],
                             bl[mf][0], bl[mf][1]);
            }
        }
    }
    __syncthreads();

    if (EPI == 0) {
        float* Yb = Yf + (size_t)b * Cout * MPTS;
        const int prt = (blockIdx.x * 4 + warp_m) * 32 + blockIdx.z; // 0..2047
#pragma unroll
        for (int of = 0; of < OFR; ++of) {
            int o = o0 + warp_o * OW + of * 16 + (lane >> 2);
#pragma unroll
            for (int hf = 0; hf < 2; ++hf) {
                int oc = o + hf * 8;
                float bs = bias[oc];
                float s = 0.f, s2 = 0.f;
#pragma unroll
                for (int mf = 0; mf < 4; ++mf) {
                    int m = m0 + warp_m * 32 + mf * 8 + 2 * (lane & 3);
                    float v0 = acc[of][mf][2 * hf]     + bs;
                    float v1 = acc[of][mf][2 * hf + 1] + bs;
                    *(float2*)&Yb[(size_t)oc * MPTS + m] = make_float2(v0, v1);
                    s  += v0 + v1;
                    s2 += v0 * v0 + v1 * v1;
                }
                s  += __shfl_xor_sync(0xffffffffu, s, 1);
                s2 += __shfl_xor_sync(0xffffffffu, s2, 1);
                s  += __shfl_xor_sync(0xffffffffu, s, 2);
                s2 += __shfl_xor_sync(0xffffffffu, s2, 2);
                if ((lane & 3) == 0) {
                    part[(size_t)(2 * oc)     * 2048 + prt] = s;
                    part[(size_t)(2 * oc + 1) * 2048 + prt] = s2;
                }
            }
        }
    } else {
        __half* SH = (__half*)smem;                 // 128 x 136
        __half* SL = SH + 128 * 136;
#pragma unroll
        for (int of = 0; of < OFR; ++of) {
            int orel0 = warp_o * OW + of * 16 + (lane >> 2);
#pragma unroll
            for (int hf = 0; hf < 2; ++hf) {
                int orel = orel0 + hf * 8;
                int o = o0 + orel;
                float bs = bias[o];
                float zv = (EPI == 2) ? zmod[(size_t)b * CW + o] : 0.f;
#pragma unroll
                for (int mf = 0; mf < 4; ++mf) {
                    int mrel = warp_m * 32 + mf * 8 + 2 * (lane & 3);
                    float v0 = acc[of][mf][2 * hf]     + bs;
                    float v1 = acc[of][mf][2 * hf + 1] + bs;
                    if (EPI == 1) { v0 = fmaxf(v0, 0.f); v1 = fmaxf(v1, 0.f); }
                    if (EPI == 2) {
                        v0 = zv * fminf(fmaxf(v0, -1.f), 1.f);
                        v1 = zv * fminf(fmaxf(v1, -1.f), 1.f);
                    }
                    __half h0 = __float2half_rn(v0), h1 = __float2half_rn(v1);
                    SH[mrel * 136 + orel]       = h0;
                    SH[(mrel + 1) * 136 + orel] = h1;
                    SL[mrel * 136 + orel]       = __float2half_rn(v0 - __half2float(h0));
                    SL[(mrel + 1) * 136 + orel] = __float2half_rn(v1 - __half2float(h1));
                }
            }
        }
        __syncthreads();
        for (int i = tid; i < 2048; i += 256) {
            int m = i >> 4, p = i & 15;
            size_t gb = ((size_t)b * MPTS + m0 + m) * Cout + o0 + p * 8;
            *(uint4*)(YH + gb) = *(uint4*)(SH + m * 136 + p * 8);
            *(uint4*)(YL + gb) = *(uint4*)(SL + m * 136 + p * 8);
        }
    }
}

// ---------------- BN finalize: partials -> folded affine (a, c) ------------
__global__ void bn_finalize_kernel(const float* __restrict__ part, int Cout,
                                   const float* __restrict__ g,
                                   const float* __restrict__ be,
                                   float* __restrict__ a_out,
                                   float* __restrict__ c_out)
{
    int o = blockIdx.x;
    const float* ps  = part + (size_t)(2 * o)     * 2048;
    const float* ps2 = part + (size_t)(2 * o + 1) * 2048;
    float s = 0.f, s2 = 0.f;
    for (int p = threadIdx.x; p < 2048; p += 256) {
        s  += ps[p];
        s2 += ps2[p];
    }
#pragma unroll
    for (int off = 16; off; off >>= 1) {
        s  += __shfl_down_sync(0xffffffffu, s,  off);
        s2 += __shfl_down_sync(0xffffffffu, s2, off);
    }
    __shared__ float sh[8], sh2[8];
    int w = threadIdx.x >> 5, l = threadIdx.x & 31;
    if (l == 0) { sh[w] = s; sh2[w] = s2; }
    __syncthreads();
    if (threadIdx.x < 8) {
        s = sh[threadIdx.x]; s2 = sh2[threadIdx.x];
#pragma unroll
        for (int off = 4; off; off >>= 1) {
            s  += __shfl_down_sync(0xffu, s,  off);
            s2 += __shfl_down_sync(0xffu, s2, off);
        }
        if (threadIdx.x == 0) {
            const float inv = 1.f / (float)(BATCH * MPTS);
            float mu  = s * inv;
            float var = s2 * inv - mu * mu;
            float aa  = g[o] * rsqrtf(var + 1e-5f);
            a_out[o] = aa;
            c_out[o] = be[o] - aa * mu;
        }
    }
}

// ---------------- 64->3 projection -> packed float4 (x,y,z,|p|^2) ----------
__global__ void out_kernel(const float* __restrict__ T3,
                           const float* __restrict__ w_out,
                           const float* __restrict__ b_out,
                           const float* __restrict__ a,
                           const float* __restrict__ c,
                           float4* __restrict__ pk)
{
    __shared__ float Ws[3][64];
    __shared__ float As[64], Cs[64];
    int tid = threadIdx.x;
    if (tid < 192) Ws[tid / 64][tid & 63] = w_out[tid];
    if (tid < 64) { As[tid] = a[tid]; Cs[tid] = c[tid]; }
    __syncthreads();

    int idx = blockIdx.x * blockDim.x + tid;
    int b = idx >> 11, m = idx & (MPTS - 1);
    const float* p = T3 + (size_t)b * 64 * MPTS + m;
    float a0 = b_out[0], a1 = b_out[1], a2 = b_out[2];
#pragma unroll 8
    for (int k = 0; k < 64; ++k) {
        float v = fmaxf(fmaf(As[k], p[(size_t)k * MPTS], Cs[k]), 0.f);
        a0 = fmaf(Ws[0][k], v, a0);
        a1 = fmaf(Ws[1][k], v, a1);
        a2 = fmaf(Ws[2][k], v, a2);
    }
    pk[idx] = make_float4(a0, a1, a2, a0 * a0 + a1 * a1 + a2 * a2);
}

// ---------------- kNN (K=8) sharpening filter (float4 smem, unroll 4) -------
__global__ __launch_bounds__(256, 2)
void graph_filter_kernel(const float4* __restrict__ pk_g,
                         float* __restrict__ out)
{
    __shared__ __align__(16) float4 pk[MPTS];
    int b = blockIdx.y;
    int tid = threadIdx.x;
    const float4* pb = pk_g + (size_t)b * MPTS;
    for (int i = tid; i < MPTS; i += 256)
        pk[i] = pb[i];
    __syncthreads();

    int p = blockIdx.x * 256 + tid;
    float4 me = pk[p];
    float nx = -2.f * me.x, ny = -2.f * me.y, nz = -2.f * me.z;

    float bd[8]; int bi[8];
#pragma unroll
    for (int j = 0; j < 8; ++j) { bd[j] = 3.4e38f; bi[j] = 0; }

    for (int n = 0; n < MPTS; n += 4) {
        float d[4];
#pragma unroll
        for (int u = 0; u < 4; ++u) {
            float4 q = pk[n + u];
            d[u] = fmaf(nx, q.x, fmaf(ny, q.y, fmaf(nz, q.z, q.w)));
        }
#pragma unroll
        for (int u = 0; u < 4; ++u) {
            if (n + u != p && d[u] < bd[7]) {
                bd[7] = d[u]; bi[7] = n + u;
#pragma unroll
                for (int j = 7; j > 0; --j)
                    if (bd[j] < bd[j - 1]) {
                        float td = bd[j]; bd[j] = bd[j - 1]; bd[j - 1] = td;
                        int   ti = bi[j]; bi[j] = bi[j - 1]; bi[j - 1] = ti;
                    }
            }
        }
    }

    float mx = 0.f, my = 0.f, mz = 0.f;
#pragma unroll
    for (int j = 0; j < 8; ++j) {
        float4 q = pk[bi[j]];
        mx += q.x; my += q.y; mz += q.z;
    }
    const float k8 = 1.f / 8.f;
    float* ob = out + (size_t)b * 3 * MPTS;
    ob[p]            = 2.f * me.x - mx * k8;
    ob[MPTS + p]     = 2.f * me.y - my * k8;
    ob[2 * MPTS + p] = 2.f * me.z - mz * k8;
}

// ---------------------------------------------------------------------------
#define STAGE_OT(OT) ((2 * (OT) + 256) * 80)
#define SMEM_OT(OT)  (2 * STAGE_OT(OT))

extern "C" void kernel_launch(void* const* d_in, const int* in_sizes, int n_in,
                              void* d_out, int out_size)
{
    const float* z     = (const float*)d_in[0];
    const float* s     = (const float*)d_in[1];
    const float* w_m1  = (const float*)d_in[2];
    const float* b_m1  = (const float*)d_in[3];
    const float* w_m2  = (const float*)d_in[4];
    const float* b_m2  = (const float*)d_in[5];
    const float* w_out = (const float*)d_in[6];
    const float* b_out = (const float*)d_in[7];
    const float* w_c [4] = {(const float*)d_in[8],  (const float*)d_in[12],
                            (const float*)d_in[16], (const float*)d_in[20]};
    const float* b_c [4] = {(const float*)d_in[9],  (const float*)d_in[13],
                            (const float*)d_in[17], (const float*)d_in[21]};
    const float* g_c [4] = {(const float*)d_in[10], (const float*)d_in[14],
                            (const float*)d_in[18], (const float*)d_in[22]};
    const float* be_c[4] = {(const float*)d_in[11], (const float*)d_in[15],
                            (const float*)d_in[19], (const float*)d_in[23]};

    float *t0, *t1, *t2, *t3, *aff_a, *aff_c, *part;
    float4* pk;
    __half *xnH, *xnL, *y1H, *y1L, *y2H, *y2L, *WH, *WL;
    cudaGetSymbolAddress((void**)&t0,    g_t0);
    cudaGetSymbolAddress((void**)&t1,    g_t1);
    cudaGetSymbolAddress((void**)&t2,    g_t2);
    cudaGetSymbolAddress((void**)&t3,    g_t3);
    cudaGetSymbolAddress((void**)&pk,    g_pk);
    cudaGetSymbolAddress((void**)&aff_a, g_aff_a);
    cudaGetSymbolAddress((void**)&aff_c, g_aff_c);
    cudaGetSymbolAddress((void**)&part,  g_part);
    cudaGetSymbolAddress((void**)&xnH,   g_xnH);
    cudaGetSymbolAddress((void**)&xnL,   g_xnL);
    cudaGetSymbolAddress((void**)&y1H,   g_y1H);
    cudaGetSymbolAddress((void**)&y1L,   g_y1L);
    cudaGetSymbolAddress((void**)&y2H,   g_y2H);
    cudaGetSymbolAddress((void**)&y2L,   g_y2L);
    cudaGetSymbolAddress((void**)&WH,    g_WH);
    cudaGetSymbolAddress((void**)&WL,    g_WL);

    cudaFuncSetAttribute(gemm_mma<128, 0, 1>, cudaFuncAttributeMaxDynamicSharedMemorySize, SMEM_OT(128));
    cudaFuncSetAttribute(gemm_mma<128, 0, 2>, cudaFuncAttributeMaxDynamicSharedMemorySize, SMEM_OT(128));
    cudaFuncSetAttribute(gemm_mma<128, 0, 0>, cudaFuncAttributeMaxDynamicSharedMemorySize, SMEM_OT(128));
    cudaFuncSetAttribute(gemm_mma<128, 1, 0>, cudaFuncAttributeMaxDynamicSharedMemorySize, SMEM_OT(128));
    cudaFuncSetAttribute(gemm_mma<64, 1, 0>,  cudaFuncAttributeMaxDynamicSharedMemorySize, SMEM_OT(64));

    // 0) fused prep: weight splits + sample normalize/split
    prep_kernel<<<2480, 256>>>(w_m1, w_m2, w_c[0], w_c[1], w_c[2], w_c[3],
                               WH, WL, s, xnH, xnL);

    // 1) map_samples1: 16 -> 256, relu, split out
    gemm_mma<128, 0, 1><<<dim3(MPTS / 128, 2, BATCH), 256, SMEM_OT(128)>>>(
        xnH, xnL, nullptr, WH + WO_1, WL + WO_1, b_m1,
        nullptr, y1H, y1L, 16, 256, nullptr, nullptr, nullptr, nullptr);

    // 2) map_samples2: 256 -> 512, z*clip, split out
    gemm_mma<128, 0, 2><<<dim3(MPTS / 128, 4, BATCH), 256, SMEM_OT(128)>>>(
        y1H, y1L, nullptr, WH + WO_2, WL + WO_2, b_m2,
        nullptr, y2H, y2L, 256, 512, nullptr, nullptr, z, nullptr);

    // 3) conv block 0: 512 -> 512, fp32 out + fused stats
    gemm_mma<128, 0, 0><<<dim3(MPTS / 128, 4, BATCH), 256, SMEM_OT(128)>>>(
        y2H, y2L, nullptr, WH + WO_3, WL + WO_3, b_c[0],
        t0, nullptr, nullptr, 512, 512, nullptr, nullptr, nullptr, part);
    bn_finalize_kernel<<<512, 256>>>(part, 512, g_c[0], be_c[0], aff_a, aff_c);

    // 4) conv block 1: relu(bn(t0)) -> 256
    gemm_mma<128, 1, 0><<<dim3(MPTS / 128, 2, BATCH), 256, SMEM_OT(128)>>>(
        nullptr, nullptr, t0, WH + WO_4, WL + WO_4, b_c[1],
        t1, nullptr, nullptr, 512, 256, aff_a, aff_c, nullptr, part);
    bn_finalize_kernel<<<256, 256>>>(part, 256, g_c[1], be_c[1],
                                     aff_a + 512, aff_c + 512);

    // 5) conv block 2: -> 128
    gemm_mma<128, 1, 0><<<dim3(MPTS / 128, 1, BATCH), 256, SMEM_OT(128)>>>(
        nullptr, nullptr, t1, WH + WO_5, WL + WO_5, b_c[2],
        t2, nullptr, nullptr, 256, 128, aff_a + 512, aff_c + 512, nullptr, part);
    bn_finalize_kernel<<<128, 256>>>(part, 128, g_c[2], be_c[2],
                                     aff_a + 1024, aff_c + 1024);

    // 6) conv block 3: -> 64
    gemm_mma<64, 1, 0><<<dim3(MPTS / 128, 1, BATCH), 256, SMEM_OT(64)>>>(
        nullptr, nullptr, t2, WH + WO_6, WL + WO_6, b_c[3],
        t3, nullptr, nullptr, 128, 64, aff_a + 1024, aff_c + 1024, nullptr, part);
    bn_finalize_kernel<<<64, 256>>>(part, 64, g_c[3], be_c[3],
                                    aff_a + 1536, aff_c + 1536);

    // 7) output projection 64 -> 3 -> packed float4
    out_kernel<<<(BATCH * MPTS) / 256, 256>>>(t3, w_out, b_out,
                                              aff_a + 1536, aff_c + 1536, pk);

    // 8) graph sharpening filter
    graph_filter_kernel<<<dim3(MPTS / 256, BATCH), 256>>>(pk, (float*)d_out);
}